// round 16
// baseline (speedup 1.0000x reference)
#include <cuda_runtime.h>
#include <cuda_bf16.h>
#include <cstdint>

// ---------------------------------------------------------------------------
// Problem constants: B=64, S=20, E=512, H=512, V=32000, C=1000
//   D1 = 11264, virtual K1 = 11776 = [enc|word|persona|h0], 4H = 2048
// ---------------------------------------------------------------------------
#define Bsz   64
#define Hdim  512
#define G4H   2048
#define Vdim  32000
#define K1v   11776

static __device__ float g_zpart[8 * Bsz * G4H];            // 4.2 MB (8 slices)
static __device__ float g_cbuf[2][Bsz * Hdim];
static __device__ float g_logits[Bsz * Vdim];              // 8.2 MB
static __device__ __nv_bfloat16 g_x1h[Bsz * K1v];          // layer-1 A hi
static __device__ __nv_bfloat16 g_x1l[Bsz * K1v];          // layer-1 A lo
static __device__ __nv_bfloat16 g_hh[2][Bsz * Hdim];       // h bf16 hi
static __device__ __nv_bfloat16 g_hl[2][Bsz * Hdim];       // h bf16 lo
static __device__ int g_bar1 = 0;                          // barrier counter A
static __device__ int g_bar2 = 0;                          // barrier counter B

__device__ __forceinline__ float sigmoidf_fast(float x) {
    return 1.0f / (1.0f + __expf(-x));
}
__device__ __forceinline__ uint32_t smem_u32(const void* p) {
    uint32_t a;
    asm("{ .reg .u64 t; cvta.to.shared.u64 t, %1; cvt.u32.u64 %0, t; }"
        : "=r"(a) : "l"(p));
    return a;
}
__device__ __forceinline__ void ldsm4(uint32_t* r, uint32_t addr) {
    asm volatile("ldmatrix.sync.aligned.m8n8.x4.shared.b16 {%0,%1,%2,%3}, [%4];"
                 : "=r"(r[0]), "=r"(r[1]), "=r"(r[2]), "=r"(r[3]) : "r"(addr));
}
__device__ __forceinline__ void ldsm4t(uint32_t* r, uint32_t addr) {
    asm volatile("ldmatrix.sync.aligned.m8n8.x4.trans.shared.b16 {%0,%1,%2,%3}, [%4];"
                 : "=r"(r[0]), "=r"(r[1]), "=r"(r[2]), "=r"(r[3]) : "r"(addr));
}
__device__ __forceinline__ void mma16816(float* d, const uint32_t* a,
                                         uint32_t b0, uint32_t b1) {
    asm volatile(
        "mma.sync.aligned.m16n8k16.row.col.f32.bf16.bf16.f32 "
        "{%0,%1,%2,%3}, {%4,%5,%6,%7}, {%8,%9}, {%0,%1,%2,%3};"
        : "+f"(d[0]), "+f"(d[1]), "+f"(d[2]), "+f"(d[3])
        : "r"(a[0]), "r"(a[1]), "r"(a[2]), "r"(a[3]), "r"(b0), "r"(b1));
}
// Dekker split of 2 floats -> packed bf16x2 hi + lo (rn-exact vs element-wise)
__device__ __forceinline__ void dek2(float x, float y, uint32_t& hp, uint32_t& lp) {
    asm("cvt.rn.bf16x2.f32 %0, %1, %2;" : "=r"(hp) : "f"(y), "f"(x));
    float fx = __uint_as_float(hp << 16);
    float fy = __uint_as_float(hp & 0xFFFF0000u);
    asm("cvt.rn.bf16x2.f32 %0, %1, %2;" : "=r"(lp) : "f"(y - fy), "f"(x - fx));
}

// ---------------------------------------------------------------------------
// shared GEMM building-block macros (used by both GEMM kernels). They
// reference local names: xhp,xlp,k0,wsplit,Wa,Wb,N,bn,bk,xm,xh2,WRAP,
// Ah,Al,Bh,Bl, nw,lr,lc, acc.
// ---------------------------------------------------------------------------
#define LOAD_A(t, S) do {                                                   \
    int kg = k0 + (t) * 32 + xh2;                                           \
    if (WRAP) kg &= 511;                                                    \
    avh0_##S = *reinterpret_cast<const uint4*>(xhp + kg);                   \
    avh1_##S = *reinterpret_cast<const uint4*>(xhp + kg + 8);               \
    avl0_##S = *reinterpret_cast<const uint4*>(xlp + kg);                   \
    avl1_##S = *reinterpret_cast<const uint4*>(xlp + kg + 8);               \
} while (0)
#define LOAD_B(t, S) do {                                                   \
    int r = k0 + (t) * 32 + bk;                                             \
    const float* p = (r < wsplit) ? (Wa + (long long)r * N)                 \
                                  : (Wb + (long long)(r - wsplit) * N);     \
    br_##S[0] = *reinterpret_cast<const float4*>(p + n0 + bn);              \
    br_##S[1] = *reinterpret_cast<const float4*>(p + n0 + bn + 4);          \
    br_##S[2] = *reinterpret_cast<const float4*>(p + n0 + bn + 8);          \
    br_##S[3] = *reinterpret_cast<const float4*>(p + n0 + bn + 12);         \
} while (0)
#define STORE_A(S) do {                                                     \
    *reinterpret_cast<uint4*>(&Ah[S][xm][xh2])     = avh0_##S;              \
    *reinterpret_cast<uint4*>(&Ah[S][xm][xh2 + 8]) = avh1_##S;              \
    *reinterpret_cast<uint4*>(&Al[S][xm][xh2])     = avl0_##S;              \
    *reinterpret_cast<uint4*>(&Al[S][xm][xh2 + 8]) = avl1_##S;              \
} while (0)
#define STORE_B(S) do {                                                     \
    _Pragma("unroll")                                                       \
    for (int i = 0; i < 4; i++) {                                           \
        float4 v = br_##S[i];                                               \
        uint32_t h01, l01, h23, l23;                                        \
        dek2(v.x, v.y, h01, l01);                                           \
        dek2(v.z, v.w, h23, l23);                                           \
        *reinterpret_cast<uint2*>(&Bh[S][bk][bn + i * 4]) = make_uint2(h01, h23); \
        *reinterpret_cast<uint2*>(&Bl[S][bk][bn + i * 4]) = make_uint2(l01, l23); \
    }                                                                       \
} while (0)
#define COMPUTE(BUF) do {                                                   \
    _Pragma("unroll")                                                       \
    for (int s = 0; s < 2; s++) {                                           \
        uint32_t bhf[4], blf[4];                                            \
        ldsm4t(bhf, smem_u32(&Bh[BUF][s * 16 + lr][nw + lc]));              \
        ldsm4t(blf, smem_u32(&Bl[BUF][s * 16 + lr][nw + lc]));              \
        _Pragma("unroll")                                                   \
        for (int mt = 0; mt < 4; mt++) {                                    \
            uint32_t ahf[4], alf[4];                                        \
            ldsm4(ahf, smem_u32(&Ah[BUF][mt * 16 + lr][s * 16 + lc]));      \
            ldsm4(alf, smem_u32(&Al[BUF][mt * 16 + lr][s * 16 + lc]));      \
            mma16816(acc[mt][0], ahf, bhf[0], bhf[1]);                      \
            mma16816(acc[mt][1], ahf, bhf[2], bhf[3]);                      \
            mma16816(acc[mt][0], ahf, blf[0], blf[1]);                      \
            mma16816(acc[mt][1], ahf, blf[2], blf[3]);                      \
            mma16816(acc[mt][0], alf, bhf[0], bhf[1]);                      \
            mma16816(acc[mt][1], alf, bhf[2], bhf[3]);                      \
        }                                                                   \
    }                                                                       \
} while (0)
// depth-2 pipelined GEMM over NT (even) tiles; results in acc
#define GEMM_LOOP(NT) do {                                                  \
    LOAD_A(0, 0); LOAD_B(0, 0);                                             \
    STORE_A(0); STORE_B(0);                                                 \
    __syncthreads();                                                        \
    LOAD_A(1, 1); LOAD_B(1, 1);                                             \
    for (int t = 0; t < (NT); t += 2) {                                     \
        if (t + 2 < (NT)) { LOAD_A(t + 2, 0); LOAD_B(t + 2, 0); }           \
        COMPUTE(0);                                                         \
        STORE_A(1); STORE_B(1);                                             \
        __syncthreads();                                                    \
        if (t + 3 < (NT)) { LOAD_A(t + 3, 1); LOAD_B(t + 3, 1); }           \
        COMPUTE(1);                                                         \
        if (t + 2 < (NT)) { STORE_A(0); STORE_B(0); }                       \
        __syncthreads();                                                    \
    }                                                                       \
} while (0)
#define EPILOGUE_Z() do {                                                   \
    _Pragma("unroll")                                                       \
    for (int mt = 0; mt < 4; mt++)                                          \
        _Pragma("unroll")                                                   \
        for (int nt = 0; nt < 2; nt++) {                                    \
            int row = mt * 16 + (lane >> 2);                                \
            int col = n0 + nw + nt * 8 + (lane & 3) * 2;                    \
            *reinterpret_cast<float2*>(&Z[(long long)row * N + col]) =      \
                make_float2(acc[mt][nt][0], acc[mt][nt][1]);                \
            *reinterpret_cast<float2*>(&Z[(long long)(row + 8) * N + col]) = \
                make_float2(acc[mt][nt][2], acc[mt][nt][3]);                \
        }                                                                   \
} while (0)
// gates math for index gid over NSL zpart slices
#define GATES_BODY(NSL, Zsrc, biasP, cprevP, cnewP, hhP, hlP, mirH, mirC) do { \
    if (gid < Bsz * (Hdim / 2)) {                                           \
        int bt = gid >> 8;                                                  \
        int j = (gid & 255) * 2;                                            \
        float2 zi = *reinterpret_cast<const float2*>((biasP) + j);          \
        float2 zf = *reinterpret_cast<const float2*>((biasP) + 512 + j);    \
        float2 zg = *reinterpret_cast<const float2*>((biasP) + 1024 + j);   \
        float2 zo = *reinterpret_cast<const float2*>((biasP) + 1536 + j);   \
        const float* p = (Zsrc) + (long long)bt * G4H + j;                  \
        _Pragma("unroll")                                                   \
        for (int s = 0; s < (NSL); s++) {                                   \
            const float* q = p + (long long)s * Bsz * G4H;                  \
            float2 a = *reinterpret_cast<const float2*>(q);                 \
            float2 b = *reinterpret_cast<const float2*>(q + 512);           \
            float2 c = *reinterpret_cast<const float2*>(q + 1024);          \
            float2 d = *reinterpret_cast<const float2*>(q + 1536);          \
            zi.x += a.x; zi.y += a.y;                                       \
            zf.x += b.x; zf.y += b.y;                                       \
            zg.x += c.x; zg.y += c.y;                                       \
            zo.x += d.x; zo.y += d.y;                                       \
        }                                                                   \
        int idx = bt * Hdim + j;                                            \
        float2 cp = *reinterpret_cast<const float2*>((cprevP) + idx);       \
        float2 cv, hv;                                                      \
        cv.x = sigmoidf_fast(zf.x) * cp.x + sigmoidf_fast(zi.x) * fmaxf(zg.x, 0.0f); \
        cv.y = sigmoidf_fast(zf.y) * cp.y + sigmoidf_fast(zi.y) * fmaxf(zg.y, 0.0f); \
        hv.x = sigmoidf_fast(zo.x) * fmaxf(cv.x, 0.0f);                     \
        hv.y = sigmoidf_fast(zo.y) * fmaxf(cv.y, 0.0f);                     \
        *reinterpret_cast<float2*>((cnewP) + idx) = cv;                     \
        uint32_t hp, lp;                                                    \
        dek2(hv.x, hv.y, hp, lp);                                           \
        (hhP)[gid] = hp;                                                    \
        (hlP)[gid] = lp;                                                    \
        if (mirH) {                                                         \
            *reinterpret_cast<float2*>((float*)(mirH) + idx) = hv;          \
            *reinterpret_cast<float2*>((float*)(mirC) + idx) = cv;          \
        }                                                                   \
    }                                                                       \
} while (0)

// ---------------------------------------------------------------------------
// xconv: build layer-1 A = [enc|word|persona[spk]|h0] as bf16 hi/lo planes.
// ---------------------------------------------------------------------------
__global__ void xconv_kernel(const float* __restrict__ enc,
                             const float* __restrict__ word,
                             const float* __restrict__ persona,
                             const float* __restrict__ h0,
                             const int* __restrict__ speaker,
                             __nv_bfloat16* __restrict__ xh,
                             __nv_bfloat16* __restrict__ xl)
{
    int idx = blockIdx.x * 128 + threadIdx.x;      // < 94208
    int row = idx / (K1v / 8);
    int q = (idx - row * (K1v / 8)) * 8;
    const float* p;
    if (q < 10240)       p = enc + (long long)row * 10240 + q;
    else if (q < 10752)  p = word + (long long)row * 512 + (q - 10240);
    else if (q < 11264)  p = persona + (long long)speaker[row] * 512 + (q - 10752);
    else                 p = h0 + (long long)row * 512 + (q - 11264);
    float4 a = *reinterpret_cast<const float4*>(p);
    float4 b = *reinterpret_cast<const float4*>(p + 4);
    uint32_t h0p, l0p, h1p, l1p, h2p, l2p, h3p, l3p;
    dek2(a.x, a.y, h0p, l0p);
    dek2(a.z, a.w, h1p, l1p);
    dek2(b.x, b.y, h2p, l2p);
    dek2(b.z, b.w, h3p, l3p);
    long long o = (long long)row * K1v + q;
    *reinterpret_cast<uint4*>(xh + o) = make_uint4(h0p, h1p, h2p, h3p);
    *reinterpret_cast<uint4*>(xl + o) = make_uint4(l0p, l1p, l2p, l3p);
}

// ---------------------------------------------------------------------------
// Layer-1 fused GEMM+gates (R15 form): K=11776, split-8, grid 32x8=256.
// Uses g_bar1 (arrive) / g_bar2 (depart+reset).
// ---------------------------------------------------------------------------
__global__ __launch_bounds__(128, 2) void layer1_kernel(
    const __nv_bfloat16* __restrict__ Xh, const __nv_bfloat16* __restrict__ Xl,
    const float* __restrict__ Wa, const float* __restrict__ Wb,
    float* __restrict__ Zall,
    const float* __restrict__ bias, const float* __restrict__ c_prev,
    float* __restrict__ c_new,
    uint32_t* __restrict__ hh_out, uint32_t* __restrict__ hl_out)
{
    __shared__ __align__(16) __nv_bfloat16 Ah[2][64][40];
    __shared__ __align__(16) __nv_bfloat16 Al[2][64][40];
    __shared__ __align__(16) __nv_bfloat16 Bh[2][32][72];
    __shared__ __align__(16) __nv_bfloat16 Bl[2][32][72];

    const int tid = threadIdx.x;
    const int lane = tid & 31;
    const int warp = tid >> 5;
    const int n0 = blockIdx.x * 64;
    const int sp = blockIdx.y;
    const int kc = 1472, N = G4H, wsplit = 11264;
    const int k0 = sp * kc;
    constexpr bool WRAP = false;
    float* Z = Zall + (long long)sp * 64 * N;

    const int xm = tid >> 1;
    const int xh2 = (tid & 1) * 16;
    const __nv_bfloat16* xhp = Xh + (long long)xm * K1v;
    const __nv_bfloat16* xlp = Xl + (long long)xm * K1v;
    const int bk = tid >> 2;
    const int bn = (tid & 3) * 16;
    const int nw = warp * 16;
    const int lr = lane & 15;
    const int lc = (lane >> 4) * 8;

    uint4 avh0_0, avh1_0, avl0_0, avl1_0;
    uint4 avh0_1, avh1_1, avl0_1, avl1_1;
    float4 br_0[4], br_1[4];

    float acc[4][2][4];
#pragma unroll
    for (int mt = 0; mt < 4; mt++)
#pragma unroll
        for (int nt = 0; nt < 2; nt++)
#pragma unroll
            for (int e = 0; e < 4; e++) acc[mt][nt][e] = 0.0f;

    GEMM_LOOP(46);          // kc/32 = 46 (even)
    EPILOGUE_Z();

    // arrive barrier
    const int G = 256;
    __threadfence();
    __syncthreads();
    if (tid == 0) {
        atomicAdd(&g_bar1, 1);
        while (*(volatile int*)&g_bar1 < G) {}
    }
    __syncthreads();
    __threadfence();

    int gid = (blockIdx.y * gridDim.x + blockIdx.x) * 128 + tid;
    GATES_BODY(8, Zall, bias, c_prev, c_new, hh_out, hl_out,
               (float*)nullptr, (float*)nullptr);

    // depart + reset
    __threadfence();
    __syncthreads();
    if (tid == 0) {
        atomicAdd(&g_bar2, 1);
        if (blockIdx.x == 0 && blockIdx.y == 0) {
            while (*(volatile int*)&g_bar2 < G) {}
            atomicExch(&g_bar1, 0);
            atomicExch(&g_bar2, 0);
        }
    }
}

// ---------------------------------------------------------------------------
// Layers 2-4 PERSISTENT kernel: grid 32x4 = 128 CTAs (always co-resident).
// Per layer: GEMM (split-4, kc=256, NT=8) -> barrier -> gates(4) -> barrier.
// Monotonic counter barrier on g_bar1 (targets phase*128); reset at end.
// ---------------------------------------------------------------------------
__global__ __launch_bounds__(128, 2) void layers234_kernel(
    __nv_bfloat16* __restrict__ hhA, __nv_bfloat16* __restrict__ hlA,  // h1 in
    __nv_bfloat16* __restrict__ hhB, __nv_bfloat16* __restrict__ hlB,
    const float* __restrict__ W2, const float* __restrict__ U2, const float* __restrict__ b2,
    const float* __restrict__ W3, const float* __restrict__ U3, const float* __restrict__ b3,
    const float* __restrict__ W4, const float* __restrict__ U4, const float* __restrict__ b4,
    float* __restrict__ cA, float* __restrict__ cB,
    float* __restrict__ Zall,
    float* __restrict__ h_mir, float* __restrict__ c_mir)
{
    __shared__ __align__(16) __nv_bfloat16 Ah[2][64][40];
    __shared__ __align__(16) __nv_bfloat16 Al[2][64][40];
    __shared__ __align__(16) __nv_bfloat16 Bh[2][32][72];
    __shared__ __align__(16) __nv_bfloat16 Bl[2][32][72];

    const int tid = threadIdx.x;
    const int lane = tid & 31;
    const int warp = tid >> 5;
    const int n0 = blockIdx.x * 64;
    const int sp = blockIdx.y;              // 0..3
    const int kc = 256, N = G4H, wsplit = 512;
    const int k0 = sp * kc;
    constexpr bool WRAP = true;
    float* Z = Zall + (long long)sp * 64 * N;

    const int xm = tid >> 1;
    const int xh2 = (tid & 1) * 16;
    const int bk = tid >> 2;
    const int bn = (tid & 3) * 16;
    const int nw = warp * 16;
    const int lr = lane & 15;
    const int lc = (lane >> 4) * 8;
    const int gid = (blockIdx.y * gridDim.x + blockIdx.x) * 128 + tid;
    const int G = 128;

    const float* WaL[3] = {W2, W3, W4};
    const float* WbL[3] = {U2, U3, U4};
    const float* bL[3]  = {b2, b3, b4};

    uint4 avh0_0, avh1_0, avl0_0, avl1_0;
    uint4 avh0_1, avh1_1, avl0_1, avl1_1;
    float4 br_0[4], br_1[4];

    int phase = 0;
#pragma unroll
    for (int l = 0; l < 3; l++) {
        const __nv_bfloat16* XhL = (l == 1) ? hhB : hhA;
        const __nv_bfloat16* XlL = (l == 1) ? hlB : hlA;
        const __nv_bfloat16* xhp = XhL + (long long)xm * Hdim;
        const __nv_bfloat16* xlp = XlL + (long long)xm * Hdim;
        const float* Wa = WaL[l];
        const float* Wb = WbL[l];

        float acc[4][2][4];
#pragma unroll
        for (int mt = 0; mt < 4; mt++)
#pragma unroll
            for (int nt = 0; nt < 2; nt++)
#pragma unroll
                for (int e = 0; e < 4; e++) acc[mt][nt][e] = 0.0f;

        GEMM_LOOP(8);       // kc/32 = 8 (even)
        EPILOGUE_Z();

        // barrier: GEMM done -> gates may read zpart
        phase++;
        __threadfence();
        __syncthreads();
        if (tid == 0) {
            atomicAdd(&g_bar1, 1);
            while (*(volatile int*)&g_bar1 < phase * G) {}
        }
        __syncthreads();
        __threadfence();

        // gates
        const float* cprev = (l == 1) ? cB : cA;
        float* cnew        = (l == 1) ? cA : cB;
        uint32_t* hhO = (uint32_t*)((l == 1) ? hhA : hhB);
        uint32_t* hlO = (uint32_t*)((l == 1) ? hlA : hlB);
        float* mH = (l == 2) ? h_mir : nullptr;
        float* mC = (l == 2) ? c_mir : nullptr;
        GATES_BODY(4, Zall, bL[l], cprev, cnew, hhO, hlO, mH, mC);

        if (l < 2) {
            // barrier: gates done -> next GEMM may read h and overwrite zpart
            phase++;
            __threadfence();
            __syncthreads();
            if (tid == 0) {
                atomicAdd(&g_bar1, 1);
                while (*(volatile int*)&g_bar1 < phase * G) {}
            }
            __syncthreads();
            __threadfence();
        }
    }

    // final arrival + counter reset (CTA (0,0)) for graph replay
    __threadfence();
    __syncthreads();
    if (tid == 0) {
        atomicAdd(&g_bar1, 1);
        if (blockIdx.x == 0 && blockIdx.y == 0) {
            while (*(volatile int*)&g_bar1 < 6 * G) {}
            atomicExch(&g_bar1, 0);
        }
    }
}

// ---------------------------------------------------------------------------
// Decoder GEMM (unfused): logits = h4 @ Wd, grid 500, NT=16.
// ---------------------------------------------------------------------------
__global__ __launch_bounds__(128, 2) void decoder_kernel(
    const __nv_bfloat16* __restrict__ Xh, const __nv_bfloat16* __restrict__ Xl,
    const float* __restrict__ Wd, float* __restrict__ Zall)
{
    __shared__ __align__(16) __nv_bfloat16 Ah[2][64][40];
    __shared__ __align__(16) __nv_bfloat16 Al[2][64][40];
    __shared__ __align__(16) __nv_bfloat16 Bh[2][32][72];
    __shared__ __align__(16) __nv_bfloat16 Bl[2][32][72];

    const int tid = threadIdx.x;
    const int lane = tid & 31;
    const int warp = tid >> 5;
    const int n0 = blockIdx.x * 64;
    const int N = Vdim, wsplit = 1 << 30;
    const int k0 = 0;
    constexpr bool WRAP = true;
    const float* Wa = Wd;
    const float* Wb = Wd;
    float* Z = Zall;

    const int xm = tid >> 1;
    const int xh2 = (tid & 1) * 16;
    const __nv_bfloat16* xhp = Xh + (long long)xm * Hdim;
    const __nv_bfloat16* xlp = Xl + (long long)xm * Hdim;
    const int bk = tid >> 2;
    const int bn = (tid & 3) * 16;
    const int nw = warp * 16;
    const int lr = lane & 15;
    const int lc = (lane >> 4) * 8;

    uint4 avh0_0, avh1_0, avl0_0, avl1_0;
    uint4 avh0_1, avh1_1, avl0_1, avl1_1;
    float4 br_0[4], br_1[4];

    float acc[4][2][4];
#pragma unroll
    for (int mt = 0; mt < 4; mt++)
#pragma unroll
        for (int nt = 0; nt < 2; nt++)
#pragma unroll
            for (int e = 0; e < 4; e++) acc[mt][nt][e] = 0.0f;

    GEMM_LOOP(16);          // 512/32 = 16 (even)
    EPILOGUE_Z();
}

// ---------------------------------------------------------------------------
// Softmax over V=32000 per batch row
// ---------------------------------------------------------------------------
__global__ void softmax_kernel(const float* __restrict__ L,
                               const float* __restrict__ bd,
                               float* __restrict__ out)
{
    const int V = Vdim;
    int b = blockIdx.x;
    int tid = threadIdx.x;
    const float* r0 = L + (long long)b * V;

    float m = -1e30f, s = 0.0f;
    for (int v = tid; v < V; v += 512) {
        float val = r0[v] + bd[v];
        float nm = fmaxf(m, val);
        s = s * __expf(m - nm) + __expf(val - nm);
        m = nm;
    }
    __shared__ float sm[512], ss[512];
    sm[tid] = m; ss[tid] = s;
    __syncthreads();
    for (int st = 256; st > 0; st >>= 1) {
        if (tid < st) {
            float m2 = sm[tid + st], s2 = ss[tid + st];
            float nm = fmaxf(sm[tid], m2);
            ss[tid] = ss[tid] * __expf(sm[tid] - nm) + s2 * __expf(m2 - nm);
            sm[tid] = nm;
        }
        __syncthreads();
    }
    float M = sm[0];
    float Sinv = 1.0f / ss[0];
    for (int v = tid; v < V; v += 512) {
        float val = r0[v] + bd[v];
        out[(long long)b * V + v] = __expf(val - M) * Sinv;
    }
}

// ---------------------------------------------------------------------------
// kernel_launch
// ---------------------------------------------------------------------------
extern "C" void kernel_launch(void* const* d_in, const int* in_sizes, int n_in,
                              void* d_out, int out_size)
{
    const float* enc     = (const float*)d_in[0];
    const float* word    = (const float*)d_in[1];
    const float* h0      = (const float*)d_in[2];
    const float* c0      = (const float*)d_in[3];
    const float* persona = (const float*)d_in[4];
    const float* W1      = (const float*)d_in[5];
    const float* U1      = (const float*)d_in[6];
    const float* b1      = (const float*)d_in[7];
    const float* W2      = (const float*)d_in[8];
    const float* U2      = (const float*)d_in[9];
    const float* b2      = (const float*)d_in[10];
    const float* W3      = (const float*)d_in[11];
    const float* U3      = (const float*)d_in[12];
    const float* b3      = (const float*)d_in[13];
    const float* W4      = (const float*)d_in[14];
    const float* U4      = (const float*)d_in[15];
    const float* b4      = (const float*)d_in[16];
    const float* Wd      = (const float*)d_in[17];
    const float* bd      = (const float*)d_in[18];
    const int*   speaker = (const int*)d_in[19];
    float* out = (float*)d_out;

    void *pz, *pc, *pl, *pxh, *pxl, *phh, *phl;
    cudaGetSymbolAddress(&pz, g_zpart);
    cudaGetSymbolAddress(&pc, g_cbuf);
    cudaGetSymbolAddress(&pl, g_logits);
    cudaGetSymbolAddress(&pxh, g_x1h);
    cudaGetSymbolAddress(&pxl, g_x1l);
    cudaGetSymbolAddress(&phh, g_hh);
    cudaGetSymbolAddress(&phl, g_hl);
    float* zp = (float*)pz;
    float* cb = (float*)pc;
    float* lg = (float*)pl;
    __nv_bfloat16* x1h = (__nv_bfloat16*)pxh;
    __nv_bfloat16* x1l = (__nv_bfloat16*)pxl;
    __nv_bfloat16* hh0 = (__nv_bfloat16*)phh;
    __nv_bfloat16* hh1 = hh0 + Bsz * Hdim;
    __nv_bfloat16* hl0 = (__nv_bfloat16*)phl;
    __nv_bfloat16* hl1 = hl0 + Bsz * Hdim;
    float* c1b = cb;
    float* c2b = cb + Bsz * Hdim;

    // 0) layer-1 A -> bf16 hi/lo planes
    xconv_kernel<<<(Bsz * K1v / 8 + 127) / 128, 128>>>(
        enc, word, persona, h0, speaker, x1h, x1l);

    // 1) layer 1 (fused gates): grid 32x8=256
    layer1_kernel<<<dim3(32, 8), 128>>>(
        x1h, x1l, W1, U1, zp, b1, c0, c1b, (uint32_t*)hh0, (uint32_t*)hl0);

    // 2) layers 2-4: ONE persistent kernel, grid 32x4=128
    layers234_kernel<<<dim3(32, 4), 128>>>(
        hh0, hl0, hh1, hl1,
        W2, U2, b2, W3, U3, b3, W4, U4, b4,
        c1b, c2b, zp,
        out + (long long)Bsz * Vdim,
        out + (long long)Bsz * Vdim + Bsz * Hdim);

    // 3) decoder: logits = h4 @ Wd, grid 500
    decoder_kernel<<<dim3(500, 1), 128>>>(hh1, hl1, Wd, lg);

    // 4) softmax -> probs
    softmax_kernel<<<Bsz, 512>>>(lg, bd, out);
}

// round 17
// speedup vs baseline: 1.0342x; 1.0342x over previous
#include <cuda_runtime.h>
#include <cuda_bf16.h>
#include <cstdint>

// ---------------------------------------------------------------------------
// Problem constants: B=64, S=20, E=512, H=512, V=32000, C=1000
//   D1 = 11264, virtual K1 = 11776 = [enc|word|persona|h0], 4H = 2048
// ---------------------------------------------------------------------------
#define Bsz   64
#define Hdim  512
#define G4H   2048
#define Vdim  32000
#define K1v   11776

static __device__ float g_zpart[8 * Bsz * G4H];            // 4.2 MB (8 slices)
static __device__ float g_cbuf[2][Bsz * Hdim];
static __device__ float g_logits[Bsz * Vdim];              // 8.2 MB
static __device__ __nv_bfloat16 g_x1h[Bsz * K1v];          // layer-1 A hi
static __device__ __nv_bfloat16 g_x1l[Bsz * K1v];          // layer-1 A lo
static __device__ __nv_bfloat16 g_hh[2][Bsz * Hdim];       // h bf16 hi
static __device__ __nv_bfloat16 g_hl[2][Bsz * Hdim];       // h bf16 lo
static __device__ int g_bar1 = 0;                          // barrier counter A
static __device__ int g_bar2 = 0;                          // barrier counter B

__device__ __forceinline__ float sigmoidf_fast(float x) {
    return 1.0f / (1.0f + __expf(-x));
}
__device__ __forceinline__ uint32_t smem_u32(const void* p) {
    uint32_t a;
    asm("{ .reg .u64 t; cvta.to.shared.u64 t, %1; cvt.u32.u64 %0, t; }"
        : "=r"(a) : "l"(p));
    return a;
}
__device__ __forceinline__ void ldsm4(uint32_t* r, uint32_t addr) {
    asm volatile("ldmatrix.sync.aligned.m8n8.x4.shared.b16 {%0,%1,%2,%3}, [%4];"
                 : "=r"(r[0]), "=r"(r[1]), "=r"(r[2]), "=r"(r[3]) : "r"(addr));
}
__device__ __forceinline__ void ldsm4t(uint32_t* r, uint32_t addr) {
    asm volatile("ldmatrix.sync.aligned.m8n8.x4.trans.shared.b16 {%0,%1,%2,%3}, [%4];"
                 : "=r"(r[0]), "=r"(r[1]), "=r"(r[2]), "=r"(r[3]) : "r"(addr));
}
__device__ __forceinline__ void mma16816(float* d, const uint32_t* a,
                                         uint32_t b0, uint32_t b1) {
    asm volatile(
        "mma.sync.aligned.m16n8k16.row.col.f32.bf16.bf16.f32 "
        "{%0,%1,%2,%3}, {%4,%5,%6,%7}, {%8,%9}, {%0,%1,%2,%3};"
        : "+f"(d[0]), "+f"(d[1]), "+f"(d[2]), "+f"(d[3])
        : "r"(a[0]), "r"(a[1]), "r"(a[2]), "r"(a[3]), "r"(b0), "r"(b1));
}
// Dekker split of 2 floats -> packed bf16x2 hi + lo (rn-exact vs element-wise)
__device__ __forceinline__ void dek2(float x, float y, uint32_t& hp, uint32_t& lp) {
    asm("cvt.rn.bf16x2.f32 %0, %1, %2;" : "=r"(hp) : "f"(y), "f"(x));
    float fx = __uint_as_float(hp << 16);
    float fy = __uint_as_float(hp & 0xFFFF0000u);
    asm("cvt.rn.bf16x2.f32 %0, %1, %2;" : "=r"(lp) : "f"(y - fy), "f"(x - fx));
}

// ---------------------------------------------------------------------------
// shared GEMM building-block macros. Local names referenced:
// xhp,xlp,k0,wsplit,Wa,Wb,N,bn,bk,xm,xh2,WRAP, Ah,Al,Bh,Bl, wm,wn,lr,lc, acc.
// Warp tiling: 2x2 -> warp covers rows [wm,wm+32) x cols [wn,wn+32).
// ---------------------------------------------------------------------------
#define LOAD_A(t, S) do {                                                   \
    int kg = k0 + (t) * 32 + xh2;                                           \
    if (WRAP) kg &= 511;                                                    \
    avh0_##S = *reinterpret_cast<const uint4*>(xhp + kg);                   \
    avh1_##S = *reinterpret_cast<const uint4*>(xhp + kg + 8);               \
    avl0_##S = *reinterpret_cast<const uint4*>(xlp + kg);                   \
    avl1_##S = *reinterpret_cast<const uint4*>(xlp + kg + 8);               \
} while (0)
#define LOAD_B(t, S) do {                                                   \
    int r = k0 + (t) * 32 + bk;                                             \
    const float* p = (r < wsplit) ? (Wa + (long long)r * N)                 \
                                  : (Wb + (long long)(r - wsplit) * N);     \
    br_##S[0] = *reinterpret_cast<const float4*>(p + n0 + bn);              \
    br_##S[1] = *reinterpret_cast<const float4*>(p + n0 + bn + 4);          \
    br_##S[2] = *reinterpret_cast<const float4*>(p + n0 + bn + 8);          \
    br_##S[3] = *reinterpret_cast<const float4*>(p + n0 + bn + 12);         \
} while (0)
#define STORE_A(S) do {                                                     \
    *reinterpret_cast<uint4*>(&Ah[S][xm][xh2])     = avh0_##S;              \
    *reinterpret_cast<uint4*>(&Ah[S][xm][xh2 + 8]) = avh1_##S;              \
    *reinterpret_cast<uint4*>(&Al[S][xm][xh2])     = avl0_##S;              \
    *reinterpret_cast<uint4*>(&Al[S][xm][xh2 + 8]) = avl1_##S;              \
} while (0)
#define STORE_B(S) do {                                                     \
    _Pragma("unroll")                                                       \
    for (int i = 0; i < 4; i++) {                                           \
        float4 v = br_##S[i];                                               \
        uint32_t h01, l01, h23, l23;                                        \
        dek2(v.x, v.y, h01, l01);                                           \
        dek2(v.z, v.w, h23, l23);                                           \
        *reinterpret_cast<uint2*>(&Bh[S][bk][bn + i * 4]) = make_uint2(h01, h23); \
        *reinterpret_cast<uint2*>(&Bl[S][bk][bn + i * 4]) = make_uint2(l01, l23); \
    }                                                                       \
} while (0)
// 2x2 warp tiling: per s, fetch warp's A half (2 m16 tiles) and B half
// (2 n16 chunks x hi/lo), issue 48 MMAs per tile with 16 LDSM.
#define COMPUTE(BUF) do {                                                   \
    _Pragma("unroll")                                                       \
    for (int s = 0; s < 2; s++) {                                           \
        uint32_t bh0[4], bh1[4], bl0[4], bl1[4];                            \
        ldsm4t(bh0, smem_u32(&Bh[BUF][s * 16 + lr][wn + lc]));              \
        ldsm4t(bh1, smem_u32(&Bh[BUF][s * 16 + lr][wn + 16 + lc]));         \
        ldsm4t(bl0, smem_u32(&Bl[BUF][s * 16 + lr][wn + lc]));              \
        ldsm4t(bl1, smem_u32(&Bl[BUF][s * 16 + lr][wn + 16 + lc]));         \
        _Pragma("unroll")                                                   \
        for (int mt = 0; mt < 2; mt++) {                                    \
            uint32_t ahf[4], alf[4];                                        \
            ldsm4(ahf, smem_u32(&Ah[BUF][wm + mt * 16 + lr][s * 16 + lc])); \
            ldsm4(alf, smem_u32(&Al[BUF][wm + mt * 16 + lr][s * 16 + lc])); \
            mma16816(acc[mt][0], ahf, bh0[0], bh0[1]);                      \
            mma16816(acc[mt][1], ahf, bh0[2], bh0[3]);                      \
            mma16816(acc[mt][2], ahf, bh1[0], bh1[1]);                      \
            mma16816(acc[mt][3], ahf, bh1[2], bh1[3]);                      \
            mma16816(acc[mt][0], ahf, bl0[0], bl0[1]);                      \
            mma16816(acc[mt][1], ahf, bl0[2], bl0[3]);                      \
            mma16816(acc[mt][2], ahf, bl1[0], bl1[1]);                      \
            mma16816(acc[mt][3], ahf, bl1[2], bl1[3]);                      \
            mma16816(acc[mt][0], alf, bh0[0], bh0[1]);                      \
            mma16816(acc[mt][1], alf, bh0[2], bh0[3]);                      \
            mma16816(acc[mt][2], alf, bh1[0], bh1[1]);                      \
            mma16816(acc[mt][3], alf, bh1[2], bh1[3]);                      \
        }                                                                   \
    }                                                                       \
} while (0)
// depth-2 pipelined GEMM over NT (even) tiles; results in acc
#define GEMM_LOOP(NT) do {                                                  \
    LOAD_A(0, 0); LOAD_B(0, 0);                                             \
    STORE_A(0); STORE_B(0);                                                 \
    __syncthreads();                                                        \
    LOAD_A(1, 1); LOAD_B(1, 1);                                             \
    for (int t = 0; t < (NT); t += 2) {                                     \
        if (t + 2 < (NT)) { LOAD_A(t + 2, 0); LOAD_B(t + 2, 0); }           \
        COMPUTE(0);                                                         \
        STORE_A(1); STORE_B(1);                                             \
        __syncthreads();                                                    \
        if (t + 3 < (NT)) { LOAD_A(t + 3, 1); LOAD_B(t + 3, 1); }           \
        COMPUTE(1);                                                         \
        if (t + 2 < (NT)) { STORE_A(0); STORE_B(0); }                       \
        __syncthreads();                                                    \
    }                                                                       \
} while (0)
#define EPILOGUE_Z() do {                                                   \
    _Pragma("unroll")                                                       \
    for (int mt = 0; mt < 2; mt++)                                          \
        _Pragma("unroll")                                                   \
        for (int nt = 0; nt < 4; nt++) {                                    \
            int row = wm + mt * 16 + (lane >> 2);                           \
            int col = n0 + wn + nt * 8 + (lane & 3) * 2;                    \
            *reinterpret_cast<float2*>(&Z[(long long)row * N + col]) =      \
                make_float2(acc[mt][nt][0], acc[mt][nt][1]);                \
            *reinterpret_cast<float2*>(&Z[(long long)(row + 8) * N + col]) = \
                make_float2(acc[mt][nt][2], acc[mt][nt][3]);                \
        }                                                                   \
} while (0)
// gates math for index gid over NSL zpart slices
#define GATES_BODY(NSL, Zsrc, biasP, cprevP, cnewP, hhP, hlP, mirH, mirC) do { \
    if (gid < Bsz * (Hdim / 2)) {                                           \
        int bt = gid >> 8;                                                  \
        int j = (gid & 255) * 2;                                            \
        float2 zi = *reinterpret_cast<const float2*>((biasP) + j);          \
        float2 zf = *reinterpret_cast<const float2*>((biasP) + 512 + j);    \
        float2 zg = *reinterpret_cast<const float2*>((biasP) + 1024 + j);   \
        float2 zo = *reinterpret_cast<const float2*>((biasP) + 1536 + j);   \
        const float* p = (Zsrc) + (long long)bt * G4H + j;                  \
        _Pragma("unroll")                                                   \
        for (int s = 0; s < (NSL); s++) {                                   \
            const float* q = p + (long long)s * Bsz * G4H;                  \
            float2 a = *reinterpret_cast<const float2*>(q);                 \
            float2 b = *reinterpret_cast<const float2*>(q + 512);           \
            float2 c = *reinterpret_cast<const float2*>(q + 1024);          \
            float2 d = *reinterpret_cast<const float2*>(q + 1536);          \
            zi.x += a.x; zi.y += a.y;                                       \
            zf.x += b.x; zf.y += b.y;                                       \
            zg.x += c.x; zg.y += c.y;                                       \
            zo.x += d.x; zo.y += d.y;                                       \
        }                                                                   \
        int idx = bt * Hdim + j;                                            \
        float2 cp = *reinterpret_cast<const float2*>((cprevP) + idx);       \
        float2 cv, hv;                                                      \
        cv.x = sigmoidf_fast(zf.x) * cp.x + sigmoidf_fast(zi.x) * fmaxf(zg.x, 0.0f); \
        cv.y = sigmoidf_fast(zf.y) * cp.y + sigmoidf_fast(zi.y) * fmaxf(zg.y, 0.0f); \
        hv.x = sigmoidf_fast(zo.x) * fmaxf(cv.x, 0.0f);                     \
        hv.y = sigmoidf_fast(zo.y) * fmaxf(cv.y, 0.0f);                     \
        *reinterpret_cast<float2*>((cnewP) + idx) = cv;                     \
        uint32_t hp, lp;                                                    \
        dek2(hv.x, hv.y, hp, lp);                                           \
        (hhP)[gid] = hp;                                                    \
        (hlP)[gid] = lp;                                                    \
        if (mirH) {                                                         \
            *reinterpret_cast<float2*>((float*)(mirH) + idx) = hv;          \
            *reinterpret_cast<float2*>((float*)(mirC) + idx) = cv;          \
        }                                                                   \
    }                                                                       \
} while (0)

// ---------------------------------------------------------------------------
// xconv: build layer-1 A = [enc|word|persona[spk]|h0] as bf16 hi/lo planes.
// ---------------------------------------------------------------------------
__global__ void xconv_kernel(const float* __restrict__ enc,
                             const float* __restrict__ word,
                             const float* __restrict__ persona,
                             const float* __restrict__ h0,
                             const int* __restrict__ speaker,
                             __nv_bfloat16* __restrict__ xh,
                             __nv_bfloat16* __restrict__ xl)
{
    int idx = blockIdx.x * 128 + threadIdx.x;      // < 94208
    int row = idx / (K1v / 8);
    int q = (idx - row * (K1v / 8)) * 8;
    const float* p;
    if (q < 10240)       p = enc + (long long)row * 10240 + q;
    else if (q < 10752)  p = word + (long long)row * 512 + (q - 10240);
    else if (q < 11264)  p = persona + (long long)speaker[row] * 512 + (q - 10752);
    else                 p = h0 + (long long)row * 512 + (q - 11264);
    float4 a = *reinterpret_cast<const float4*>(p);
    float4 b = *reinterpret_cast<const float4*>(p + 4);
    uint32_t h0p, l0p, h1p, l1p, h2p, l2p, h3p, l3p;
    dek2(a.x, a.y, h0p, l0p);
    dek2(a.z, a.w, h1p, l1p);
    dek2(b.x, b.y, h2p, l2p);
    dek2(b.z, b.w, h3p, l3p);
    long long o = (long long)row * K1v + q;
    *reinterpret_cast<uint4*>(xh + o) = make_uint4(h0p, h1p, h2p, h3p);
    *reinterpret_cast<uint4*>(xl + o) = make_uint4(l0p, l1p, l2p, l3p);
}

// ---------------------------------------------------------------------------
// Layer-1 fused GEMM+gates: K=11776, split-8, grid 32x8=256.
// ---------------------------------------------------------------------------
__global__ __launch_bounds__(128, 2) void layer1_kernel(
    const __nv_bfloat16* __restrict__ Xh, const __nv_bfloat16* __restrict__ Xl,
    const float* __restrict__ Wa, const float* __restrict__ Wb,
    float* __restrict__ Zall,
    const float* __restrict__ bias, const float* __restrict__ c_prev,
    float* __restrict__ c_new,
    uint32_t* __restrict__ hh_out, uint32_t* __restrict__ hl_out)
{
    __shared__ __align__(16) __nv_bfloat16 Ah[2][64][40];
    __shared__ __align__(16) __nv_bfloat16 Al[2][64][40];
    __shared__ __align__(16) __nv_bfloat16 Bh[2][32][72];
    __shared__ __align__(16) __nv_bfloat16 Bl[2][32][72];

    const int tid = threadIdx.x;
    const int lane = tid & 31;
    const int warp = tid >> 5;
    const int n0 = blockIdx.x * 64;
    const int sp = blockIdx.y;
    const int kc = 1472, N = G4H, wsplit = 11264;
    const int k0 = sp * kc;
    constexpr bool WRAP = false;
    float* Z = Zall + (long long)sp * 64 * N;

    const int xm = tid >> 1;
    const int xh2 = (tid & 1) * 16;
    const __nv_bfloat16* xhp = Xh + (long long)xm * K1v;
    const __nv_bfloat16* xlp = Xl + (long long)xm * K1v;
    const int bk = tid >> 2;
    const int bn = (tid & 3) * 16;
    const int wm = (warp & 1) * 32;
    const int wn = (warp >> 1) * 32;
    const int lr = lane & 15;
    const int lc = (lane >> 4) * 8;

    uint4 avh0_0, avh1_0, avl0_0, avl1_0;
    uint4 avh0_1, avh1_1, avl0_1, avl1_1;
    float4 br_0[4], br_1[4];

    float acc[2][4][4];
#pragma unroll
    for (int mt = 0; mt < 2; mt++)
#pragma unroll
        for (int nt = 0; nt < 4; nt++)
#pragma unroll
            for (int e = 0; e < 4; e++) acc[mt][nt][e] = 0.0f;

    GEMM_LOOP(46);          // kc/32 = 46 (even)
    EPILOGUE_Z();

    // arrive barrier
    const int G = 256;
    __threadfence();
    __syncthreads();
    if (tid == 0) {
        atomicAdd(&g_bar1, 1);
        while (*(volatile int*)&g_bar1 < G) {}
    }
    __syncthreads();
    __threadfence();

    int gid = (blockIdx.y * gridDim.x + blockIdx.x) * 128 + tid;
    GATES_BODY(8, Zall, bias, c_prev, c_new, hh_out, hl_out,
               (float*)nullptr, (float*)nullptr);

    // depart + reset
    __threadfence();
    __syncthreads();
    if (tid == 0) {
        atomicAdd(&g_bar2, 1);
        if (blockIdx.x == 0 && blockIdx.y == 0) {
            while (*(volatile int*)&g_bar2 < G) {}
            atomicExch(&g_bar1, 0);
            atomicExch(&g_bar2, 0);
        }
    }
}

// ---------------------------------------------------------------------------
// Layers 2-4 PERSISTENT kernel: grid 32x4 = 128 CTAs (always co-resident).
// Per layer: GEMM (split-4, kc=256, NT=8) -> barrier -> gates(4) -> barrier.
// ---------------------------------------------------------------------------
__global__ __launch_bounds__(128, 2) void layers234_kernel(
    __nv_bfloat16* __restrict__ hhA, __nv_bfloat16* __restrict__ hlA,  // h1 in
    __nv_bfloat16* __restrict__ hhB, __nv_bfloat16* __restrict__ hlB,
    const float* __restrict__ W2, const float* __restrict__ U2, const float* __restrict__ b2,
    const float* __restrict__ W3, const float* __restrict__ U3, const float* __restrict__ b3,
    const float* __restrict__ W4, const float* __restrict__ U4, const float* __restrict__ b4,
    float* __restrict__ cA, float* __restrict__ cB,
    float* __restrict__ Zall,
    float* __restrict__ h_mir, float* __restrict__ c_mir)
{
    __shared__ __align__(16) __nv_bfloat16 Ah[2][64][40];
    __shared__ __align__(16) __nv_bfloat16 Al[2][64][40];
    __shared__ __align__(16) __nv_bfloat16 Bh[2][32][72];
    __shared__ __align__(16) __nv_bfloat16 Bl[2][32][72];

    const int tid = threadIdx.x;
    const int lane = tid & 31;
    const int warp = tid >> 5;
    const int n0 = blockIdx.x * 64;
    const int sp = blockIdx.y;              // 0..3
    const int kc = 256, N = G4H, wsplit = 512;
    const int k0 = sp * kc;
    constexpr bool WRAP = true;
    float* Z = Zall + (long long)sp * 64 * N;

    const int xm = tid >> 1;
    const int xh2 = (tid & 1) * 16;
    const int bk = tid >> 2;
    const int bn = (tid & 3) * 16;
    const int wm = (warp & 1) * 32;
    const int wn = (warp >> 1) * 32;
    const int lr = lane & 15;
    const int lc = (lane >> 4) * 8;
    const int gid = (blockIdx.y * gridDim.x + blockIdx.x) * 128 + tid;
    const int G = 128;

    const float* WaL[3] = {W2, W3, W4};
    const float* WbL[3] = {U2, U3, U4};
    const float* bL[3]  = {b2, b3, b4};

    uint4 avh0_0, avh1_0, avl0_0, avl1_0;
    uint4 avh0_1, avh1_1, avl0_1, avl1_1;
    float4 br_0[4], br_1[4];

    int phase = 0;
#pragma unroll
    for (int l = 0; l < 3; l++) {
        const __nv_bfloat16* XhL = (l == 1) ? hhB : hhA;
        const __nv_bfloat16* XlL = (l == 1) ? hlB : hlA;
        const __nv_bfloat16* xhp = XhL + (long long)xm * Hdim;
        const __nv_bfloat16* xlp = XlL + (long long)xm * Hdim;
        const float* Wa = WaL[l];
        const float* Wb = WbL[l];

        float acc[2][4][4];
#pragma unroll
        for (int mt = 0; mt < 2; mt++)
#pragma unroll
            for (int nt = 0; nt < 4; nt++)
#pragma unroll
                for (int e = 0; e < 4; e++) acc[mt][nt][e] = 0.0f;

        GEMM_LOOP(8);       // kc/32 = 8 (even)
        EPILOGUE_Z();

        // barrier: GEMM done -> gates may read zpart
        phase++;
        __threadfence();
        __syncthreads();
        if (tid == 0) {
            atomicAdd(&g_bar1, 1);
            while (*(volatile int*)&g_bar1 < phase * G) {}
        }
        __syncthreads();
        __threadfence();

        // gates
        const float* cprev = (l == 1) ? cB : cA;
        float* cnew        = (l == 1) ? cA : cB;
        uint32_t* hhO = (uint32_t*)((l == 1) ? hhA : hhB);
        uint32_t* hlO = (uint32_t*)((l == 1) ? hlA : hlB);
        float* mH = (l == 2) ? h_mir : nullptr;
        float* mC = (l == 2) ? c_mir : nullptr;
        GATES_BODY(4, Zall, bL[l], cprev, cnew, hhO, hlO, mH, mC);

        if (l < 2) {
            phase++;
            __threadfence();
            __syncthreads();
            if (tid == 0) {
                atomicAdd(&g_bar1, 1);
                while (*(volatile int*)&g_bar1 < phase * G) {}
            }
            __syncthreads();
            __threadfence();
        }
    }

    // final arrival + counter reset (CTA (0,0)) for graph replay
    __threadfence();
    __syncthreads();
    if (tid == 0) {
        atomicAdd(&g_bar1, 1);
        if (blockIdx.x == 0 && blockIdx.y == 0) {
            while (*(volatile int*)&g_bar1 < 6 * G) {}
            atomicExch(&g_bar1, 0);
        }
    }
}

// ---------------------------------------------------------------------------
// Decoder GEMM (unfused): logits = h4 @ Wd, grid 500, NT=16.
// ---------------------------------------------------------------------------
__global__ __launch_bounds__(128, 2) void decoder_kernel(
    const __nv_bfloat16* __restrict__ Xh, const __nv_bfloat16* __restrict__ Xl,
    const float* __restrict__ Wd, float* __restrict__ Zall)
{
    __shared__ __align__(16) __nv_bfloat16 Ah[2][64][40];
    __shared__ __align__(16) __nv_bfloat16 Al[2][64][40];
    __shared__ __align__(16) __nv_bfloat16 Bh[2][32][72];
    __shared__ __align__(16) __nv_bfloat16 Bl[2][32][72];

    const int tid = threadIdx.x;
    const int lane = tid & 31;
    const int warp = tid >> 5;
    const int n0 = blockIdx.x * 64;
    const int N = Vdim, wsplit = 1 << 30;
    const int k0 = 0;
    constexpr bool WRAP = true;
    const float* Wa = Wd;
    const float* Wb = Wd;
    float* Z = Zall;

    const int xm = tid >> 1;
    const int xh2 = (tid & 1) * 16;
    const __nv_bfloat16* xhp = Xh + (long long)xm * Hdim;
    const __nv_bfloat16* xlp = Xl + (long long)xm * Hdim;
    const int bk = tid >> 2;
    const int bn = (tid & 3) * 16;
    const int wm = (warp & 1) * 32;
    const int wn = (warp >> 1) * 32;
    const int lr = lane & 15;
    const int lc = (lane >> 4) * 8;

    uint4 avh0_0, avh1_0, avl0_0, avl1_0;
    uint4 avh0_1, avh1_1, avl0_1, avl1_1;
    float4 br_0[4], br_1[4];

    float acc[2][4][4];
#pragma unroll
    for (int mt = 0; mt < 2; mt++)
#pragma unroll
        for (int nt = 0; nt < 4; nt++)
#pragma unroll
            for (int e = 0; e < 4; e++) acc[mt][nt][e] = 0.0f;

    GEMM_LOOP(16);          // 512/32 = 16 (even)
    EPILOGUE_Z();
}

// ---------------------------------------------------------------------------
// Softmax over V=32000 per batch row
// ---------------------------------------------------------------------------
__global__ void softmax_kernel(const float* __restrict__ L,
                               const float* __restrict__ bd,
                               float* __restrict__ out)
{
    const int V = Vdim;
    int b = blockIdx.x;
    int tid = threadIdx.x;
    const float* r0 = L + (long long)b * V;

    float m = -1e30f, s = 0.0f;
    for (int v = tid; v < V; v += 512) {
        float val = r0[v] + bd[v];
        float nm = fmaxf(m, val);
        s = s * __expf(m - nm) + __expf(val - nm);
        m = nm;
    }
    __shared__ float sm[512], ss[512];
    sm[tid] = m; ss[tid] = s;
    __syncthreads();
    for (int st = 256; st > 0; st >>= 1) {
        if (tid < st) {
            float m2 = sm[tid + st], s2 = ss[tid + st];
            float nm = fmaxf(sm[tid], m2);
            ss[tid] = ss[tid] * __expf(sm[tid] - nm) + s2 * __expf(m2 - nm);
            sm[tid] = nm;
        }
        __syncthreads();
    }
    float M = sm[0];
    float Sinv = 1.0f / ss[0];
    for (int v = tid; v < V; v += 512) {
        float val = r0[v] + bd[v];
        out[(long long)b * V + v] = __expf(val - M) * Sinv;
    }
}

// ---------------------------------------------------------------------------
// kernel_launch
// ---------------------------------------------------------------------------
extern "C" void kernel_launch(void* const* d_in, const int* in_sizes, int n_in,
                              void* d_out, int out_size)
{
    const float* enc     = (const float*)d_in[0];
    const float* word    = (const float*)d_in[1];
    const float* h0      = (const float*)d_in[2];
    const float* c0      = (const float*)d_in[3];
    const float* persona = (const float*)d_in[4];
    const float* W1      = (const float*)d_in[5];
    const float* U1      = (const float*)d_in[6];
    const float* b1      = (const float*)d_in[7];
    const float* W2      = (const float*)d_in[8];
    const float* U2      = (const float*)d_in[9];
    const float* b2      = (const float*)d_in[10];
    const float* W3      = (const float*)d_in[11];
    const float* U3      = (const float*)d_in[12];
    const float* b3      = (const float*)d_in[13];
    const float* W4      = (const float*)d_in[14];
    const float* U4      = (const float*)d_in[15];
    const float* b4      = (const float*)d_in[16];
    const float* Wd      = (const float*)d_in[17];
    const float* bd      = (const float*)d_in[18];
    const int*   speaker = (const int*)d_in[19];
    float* out = (float*)d_out;

    void *pz, *pc, *pl, *pxh, *pxl, *phh, *phl;
    cudaGetSymbolAddress(&pz, g_zpart);
    cudaGetSymbolAddress(&pc, g_cbuf);
    cudaGetSymbolAddress(&pl, g_logits);
    cudaGetSymbolAddress(&pxh, g_x1h);
    cudaGetSymbolAddress(&pxl, g_x1l);
    cudaGetSymbolAddress(&phh, g_hh);
    cudaGetSymbolAddress(&phl, g_hl);
    float* zp = (float*)pz;
    float* cb = (float*)pc;
    float* lg = (float*)pl;
    __nv_bfloat16* x1h = (__nv_bfloat16*)pxh;
    __nv_bfloat16* x1l = (__nv_bfloat16*)pxl;
    __nv_bfloat16* hh0 = (__nv_bfloat16*)phh;
    __nv_bfloat16* hh1 = hh0 + Bsz * Hdim;
    __nv_bfloat16* hl0 = (__nv_bfloat16*)phl;
    __nv_bfloat16* hl1 = hl0 + Bsz * Hdim;
    float* c1b = cb;
    float* c2b = cb + Bsz * Hdim;

    // 0) layer-1 A -> bf16 hi/lo planes
    xconv_kernel<<<(Bsz * K1v / 8 + 127) / 128, 128>>>(
        enc, word, persona, h0, speaker, x1h, x1l);

    // 1) layer 1 (fused gates): grid 32x8=256
    layer1_kernel<<<dim3(32, 8), 128>>>(
        x1h, x1l, W1, U1, zp, b1, c0, c1b, (uint32_t*)hh0, (uint32_t*)hl0);

    // 2) layers 2-4: ONE persistent kernel, grid 32x4=128
    layers234_kernel<<<dim3(32, 4), 128>>>(
        hh0, hl0, hh1, hl1,
        W2, U2, b2, W3, U3, b3, W4, U4, b4,
        c1b, c2b, zp,
        out + (long long)Bsz * Vdim,
        out + (long long)Bsz * Vdim + Bsz * Hdim);

    // 3) decoder: logits = h4 @ Wd, grid 500
    decoder_kernel<<<dim3(500, 1), 128>>>(hh1, hl1, Wd, lg);

    // 4) softmax -> probs
    softmax_kernel<<<Bsz, 512>>>(lg, bd, out);
}